// round 1
// baseline (speedup 1.0000x reference)
#include <cuda_runtime.h>
#include <math.h>

#define BATCH 2
#define TSEQ  4096
#define NH    16
#define HD    64
#define CEMB  1024
#define MROWS (BATCH*TSEQ)          // 8192
#define SCALE 0.125f                // 1/sqrt(64)

// ---------------- scratch (device globals: no runtime allocation) ------------
__device__ float g_Q[(size_t)BATCH*NH*TSEQ*HD];
__device__ float g_K[(size_t)BATCH*NH*TSEQ*HD];
__device__ float g_V[(size_t)BATCH*NH*TSEQ*HD];
__device__ float g_Y[(size_t)BATCH*TSEQ*CEMB];

// ---------------- f32x2 packed-FMA helpers ----------------------------------
__device__ __forceinline__ unsigned long long pk2(float lo, float hi) {
    unsigned long long r;
    asm("mov.b64 %0, {%1, %2};" : "=l"(r)
        : "r"(__float_as_uint(lo)), "r"(__float_as_uint(hi)));
    return r;
}
__device__ __forceinline__ void fma2(unsigned long long &d,
                                     unsigned long long a,
                                     unsigned long long b) {
    asm("fma.rn.f32x2 %0, %1, %2, %0;" : "+l"(d) : "l"(a), "l"(b));
}
__device__ __forceinline__ float2 upk2(unsigned long long v) {
    unsigned int lo, hi;
    asm("mov.b64 {%0, %1}, %2;" : "=r"(lo), "=r"(hi) : "l"(v));
    return make_float2(__uint_as_float(lo), __uint_as_float(hi));
}

// ---------------- GEMM: C = A @ B + bias  (f32x2 inner) ----------------------
// MODE 0: A = x [8192,1024], B = w_qkv [1024,3072]; epilogue scatters into
//         g_Q/g_K/g_V in [b,h,t,d] layout.
// MODE 1: A = g_Y [8192,1024], B = w_proj [1024,1024]; epilogue -> out.
#define GBM 128
#define GBN 128
#define GBK 16
#define ASTR 132

template <int MODE>
__global__ __launch_bounds__(256, 2)
void gemm_f32x2(const float* __restrict__ A, const float* __restrict__ B,
                const float* __restrict__ bias, float* __restrict__ out,
                int N, int K)
{
    __shared__ __align__(16) float As[GBK * ASTR];
    __shared__ __align__(16) float Bs[GBK * GBN];

    const float* Aeff = (MODE == 1) ? g_Y : A;

    int tid = threadIdx.x;
    int mBase = blockIdx.y * GBM;
    int nBase = blockIdx.x * GBN;
    int ty = tid >> 4;     // 0..15 -> rows ty*8..
    int tx = tid & 15;     // 0..15 -> cols tx*8..

    unsigned long long acc[8][4];
#pragma unroll
    for (int i = 0; i < 8; i++)
#pragma unroll
        for (int j = 0; j < 4; j++) acc[i][j] = 0ull;

    for (int k0 = 0; k0 < K; k0 += GBK) {
        // load A tile (128x16) transposed into As[k][m]
#pragma unroll
        for (int f = tid; f < 512; f += 256) {
            int row = f >> 2, kg = f & 3;
            float4 v = *(const float4*)&Aeff[(size_t)(mBase + row) * K + k0 + kg * 4];
            As[(kg * 4 + 0) * ASTR + row] = v.x;
            As[(kg * 4 + 1) * ASTR + row] = v.y;
            As[(kg * 4 + 2) * ASTR + row] = v.z;
            As[(kg * 4 + 3) * ASTR + row] = v.w;
        }
        // load B tile (16x128) row-major
#pragma unroll
        for (int f = tid; f < 512; f += 256) {
            int kr = f >> 5, ng = f & 31;
            *(float4*)&Bs[kr * GBN + ng * 4] =
                *(const float4*)&B[(size_t)(k0 + kr) * N + nBase + ng * 4];
        }
        __syncthreads();

#pragma unroll
        for (int kk = 0; kk < GBK; kk++) {
            float4 a0 = *(const float4*)&As[kk * ASTR + ty * 8];
            float4 a1 = *(const float4*)&As[kk * ASTR + ty * 8 + 4];
            ulonglong2 b0 = *(const ulonglong2*)&Bs[kk * GBN + tx * 8];
            ulonglong2 b1 = *(const ulonglong2*)&Bs[kk * GBN + tx * 8 + 4];
            unsigned long long bp[4] = { b0.x, b0.y, b1.x, b1.y };
            float av[8] = { a0.x, a0.y, a0.z, a0.w, a1.x, a1.y, a1.z, a1.w };
#pragma unroll
            for (int i = 0; i < 8; i++) {
                unsigned long long as = pk2(av[i], av[i]);
#pragma unroll
                for (int j = 0; j < 4; j++) fma2(acc[i][j], as, bp[j]);
            }
        }
        __syncthreads();
    }

    // epilogue
#pragma unroll
    for (int i = 0; i < 8; i++) {
        int m = mBase + ty * 8 + i;
#pragma unroll
        for (int j = 0; j < 4; j++) {
            float2 v = upk2(acc[i][j]);
            int n = nBase + tx * 8 + j * 2;
            float o0 = v.x + bias[n];
            float o1 = v.y + bias[n + 1];
            if (MODE == 0) {
                int b = m >> 12, tl = m & 4095;
                int sect = n >> 10, c = n & 1023;
                int head = c >> 6, d = c & 63;
                float* dst = (sect == 0) ? g_Q : (sect == 1) ? g_K : g_V;
                size_t off = (((size_t)b * NH + head) * TSEQ + tl) * HD + d;
                *(float2*)&dst[off] = make_float2(o0, o1);
            } else {
                *(float2*)&out[(size_t)m * N + n] = make_float2(o0, o1);
            }
        }
    }
}

// ---------------- block-sparse flash attention -------------------------------
// grid = (32 query-blocks, 32 b*h), 512 threads.
// Dense key blocks: {max(qb-2,0)..qb} (+ block 0 cols<16 when qb>=3).
// Strided diagonals: kb in [0, qb-3], key j = kb*128 + (i mod 128),
// (skipping rows<16 at kb=0 which are covered by the global pass).
#define BQ    128
#define QSTR  68
#define KTSTR 132
#define VSTR  68
#define SSTR  132
#define ATTN_SMEM ((128*QSTR + 64*KTSTR + 128*VSTR + 128*SSTR + 3*128) * 4)

__global__ __launch_bounds__(512, 1)
void attn_kernel()
{
    extern __shared__ float sm[];
    float* Qs   = sm;                    // [128][QSTR]
    float* Kt   = Qs + 128 * QSTR;       // [64][KTSTR]  (d-major K tile)
    float* Vs   = Kt + 64 * KTSTR;       // [128][VSTR]
    float* Ss   = Vs + 128 * VSTR;       // [128][SSTR]
    float* mrow = Ss + 128 * SSTR;       // [128]
    float* lrow = mrow + 128;            // [128]
    float* rsc  = lrow + 128;            // [128]

    int tid = threadIdx.x;
    int qb = blockIdx.x;
    int bh = blockIdx.y;

    const float* Qg = g_Q + (size_t)bh * TSEQ * HD + (size_t)qb * BQ * HD;
    const float* Kg = g_K + (size_t)bh * TSEQ * HD;
    const float* Vg = g_V + (size_t)bh * TSEQ * HD;

    // stage Q block
#pragma unroll
    for (int e = tid; e < BQ * 16; e += 512) {
        int row = e >> 4, c4 = e & 15;
        *(float4*)&Qs[row * QSTR + c4 * 4] = *(const float4*)&Qg[row * HD + c4 * 4];
    }
    if (tid < 128) { mrow[tid] = -1e30f; lrow[tid] = 0.f; }

    float acc[4][4];
#pragma unroll
    for (int k = 0; k < 4; k++)
#pragma unroll
        for (int u = 0; u < 4; u++) acc[k][u] = 0.f;

    int rg = tid >> 4;   // row group: rows rg*4..rg*4+3
    int dq = tid & 15;   // dim quad:  dims dq*4..dq*4+3

    __syncthreads();

    // ---------------- dense key blocks ----------------
    int kb_lo = (qb - 2 > 0) ? qb - 2 : 0;
    int ndense = (qb - kb_lo + 1) + ((kb_lo > 0) ? 1 : 0);
    for (int it = 0; it < ndense; it++) {
        int kb, jmax;
        if (it <= qb - kb_lo) { kb = kb_lo + it; jmax = 128; }
        else                  { kb = 0;          jmax = 16;  }

        // stage V (row-major, coalesced loads)
        for (int e = tid; e < jmax * 16; e += 512) {
            int row = e >> 4, c4 = e & 15;
            *(float4*)&Vs[row * VSTR + c4 * 4] =
                *(const float4*)&Vg[(size_t)(kb * BQ + row) * HD + c4 * 4];
        }
        // stage K transposed (row-fast mapping -> conflict-free smem stores)
        for (int e = tid; e < jmax * 16; e += 512) {
            int row = e & (jmax - 1), c4 = e / jmax;
            float4 kvv = *(const float4*)&Kg[(size_t)(kb * BQ + row) * HD + c4 * 4];
            Kt[(c4 * 4 + 0) * KTSTR + row] = kvv.x;
            Kt[(c4 * 4 + 1) * KTSTR + row] = kvv.y;
            Kt[(c4 * 4 + 2) * KTSTR + row] = kvv.z;
            Kt[(c4 * 4 + 3) * KTSTR + row] = kvv.w;
        }
        __syncthreads();

        // S = scale * Q K^T with sparse-causal mask
        {
            int sy = tid >> 5, sx = tid & 31;
            int r0 = sy * 8, c0 = sx * 4;
            if (c0 < jmax) {
                float s[8][4];
#pragma unroll
                for (int ii = 0; ii < 8; ii++)
#pragma unroll
                    for (int jj = 0; jj < 4; jj++) s[ii][jj] = 0.f;
#pragma unroll 8
                for (int d = 0; d < HD; d++) {
                    float4 kv = *(const float4*)&Kt[d * KTSTR + c0];
#pragma unroll
                    for (int ii = 0; ii < 8; ii++) {
                        float qv = Qs[(r0 + ii) * QSTR + d];
                        s[ii][0] += qv * kv.x;
                        s[ii][1] += qv * kv.y;
                        s[ii][2] += qv * kv.z;
                        s[ii][3] += qv * kv.w;
                    }
                }
                int ib = qb * BQ;
#pragma unroll
                for (int ii = 0; ii < 8; ii++) {
                    int i = ib + r0 + ii;
                    float ov[4];
#pragma unroll
                    for (int jj = 0; jj < 4; jj++) {
                        int j = kb * BQ + c0 + jj;
                        int diff = i - j;
                        bool ok = (diff >= 0) &&
                                  ((diff < 256) || ((diff & 127) == 0) || (j < 16));
                        ov[jj] = ok ? s[ii][jj] * SCALE : -1e30f;
                    }
                    *(float4*)&Ss[(r0 + ii) * SSTR + c0] =
                        make_float4(ov[0], ov[1], ov[2], ov[3]);
                }
            }
        }
        __syncthreads();

        // online softmax update (4 threads per row)
        {
            int r = tid >> 2, part = tid & 3;
            int jbeg = part * 32;
            int jend = (jbeg + 32 < jmax) ? jbeg + 32 : jmax;
            float mx = -1e30f;
            for (int j = jbeg; j < jend; j++) mx = fmaxf(mx, Ss[r * SSTR + j]);
            mx = fmaxf(mx, __shfl_xor_sync(0xffffffffu, mx, 1));
            mx = fmaxf(mx, __shfl_xor_sync(0xffffffffu, mx, 2));
            float mold = mrow[r];
            float mnew = fmaxf(mold, mx);
            float cs = __expf(mold - mnew);
            float sum = 0.f;
            for (int j = jbeg; j < jend; j++) {
                float p = __expf(Ss[r * SSTR + j] - mnew);
                Ss[r * SSTR + j] = p;
                sum += p;
            }
            sum += __shfl_xor_sync(0xffffffffu, sum, 1);
            sum += __shfl_xor_sync(0xffffffffu, sum, 2);
            if (part == 0) {
                mrow[r] = mnew;
                lrow[r] = lrow[r] * cs + sum;
                rsc[r] = cs;
            }
        }
        __syncthreads();

        // PV accumulate
        {
#pragma unroll
            for (int k = 0; k < 4; k++) {
                float cs = rsc[rg * 4 + k];
                acc[k][0] *= cs; acc[k][1] *= cs; acc[k][2] *= cs; acc[k][3] *= cs;
            }
            for (int j = 0; j < jmax; j += 4) {
                float pv[4][4];
#pragma unroll
                for (int k = 0; k < 4; k++)
                    *(float4*)&pv[k][0] = *(const float4*)&Ss[(rg * 4 + k) * SSTR + j];
#pragma unroll
                for (int u = 0; u < 4; u++) {
                    float4 v = *(const float4*)&Vs[(j + u) * VSTR + dq * 4];
#pragma unroll
                    for (int k = 0; k < 4; k++) {
                        float p = pv[k][u];
                        acc[k][0] += p * v.x;
                        acc[k][1] += p * v.y;
                        acc[k][2] += p * v.z;
                        acc[k][3] += p * v.w;
                    }
                }
            }
        }
        __syncthreads();
    }

    // ---------------- strided diagonals (kb = 0..qb-3) ----------------
    int nkb = qb - 2;
    if (nkb > 0) {
        // score phase: 4 threads per (row, kb) dot
        int r = tid >> 2, part = tid & 3;
        for (int kb = 0; kb < nkb; kb++) {
            if (kb == 0 && r < 16) {
                if (part == 0) Ss[r * SSTR + kb] = -1e30f;   // covered by global pass
            } else {
                int j = kb * BQ + r;
                const float* kp = &Kg[(size_t)j * HD + part * 16];
                const float* qp = &Qs[r * QSTR + part * 16];
                float ps = 0.f;
#pragma unroll
                for (int u = 0; u < 4; u++) {
                    float4 a = *(const float4*)&kp[u * 4];
                    float4 b = *(const float4*)&qp[u * 4];
                    ps += a.x * b.x + a.y * b.y + a.z * b.z + a.w * b.w;
                }
                ps += __shfl_xor_sync(0xffffffffu, ps, 1);
                ps += __shfl_xor_sync(0xffffffffu, ps, 2);
                if (part == 0) Ss[r * SSTR + kb] = ps * SCALE;
            }
        }
        __syncthreads();

        // merge into running softmax (one rescale for all strided keys)
        if (tid < 128) {
            int rr = tid;
            float mold = mrow[rr];
            float mx = mold;
            for (int kb = 0; kb < nkb; kb++) mx = fmaxf(mx, Ss[rr * SSTR + kb]);
            float cs = __expf(mold - mx);
            float sum = 0.f;
            for (int kb = 0; kb < nkb; kb++) {
                float p = __expf(Ss[rr * SSTR + kb] - mx);
                Ss[rr * SSTR + kb] = p;
                sum += p;
            }
            mrow[rr] = mx;
            lrow[rr] = lrow[rr] * cs + sum;
            rsc[rr] = cs;
        }
        __syncthreads();

        // gathered PV over the strided keys (coalesced 256B V-row reads)
#pragma unroll
        for (int k = 0; k < 4; k++) {
            float cs = rsc[rg * 4 + k];
            acc[k][0] *= cs; acc[k][1] *= cs; acc[k][2] *= cs; acc[k][3] *= cs;
        }
        for (int kb = 0; kb < nkb; kb++) {
#pragma unroll
            for (int k = 0; k < 4; k++) {
                int rr = rg * 4 + k;
                float p = Ss[rr * SSTR + kb];
                float4 v = *(const float4*)&Vg[(size_t)(kb * BQ + rr) * HD + dq * 4];
                acc[k][0] += p * v.x;
                acc[k][1] += p * v.y;
                acc[k][2] += p * v.z;
                acc[k][3] += p * v.w;
            }
        }
    }

    // ---------------- normalize + write y in [b,t,C] ----------------
    int b = bh >> 4, h = bh & 15;
#pragma unroll
    for (int k = 0; k < 4; k++) {
        int rr = rg * 4 + k;
        float inv = 1.f / lrow[rr];
        int i = qb * BQ + rr;
        float4 o = make_float4(acc[k][0] * inv, acc[k][1] * inv,
                               acc[k][2] * inv, acc[k][3] * inv);
        *(float4*)&g_Y[((size_t)b * TSEQ + i) * CEMB + h * HD + dq * 4] = o;
    }
}

// ---------------- launch -----------------------------------------------------
extern "C" void kernel_launch(void* const* d_in, const int* in_sizes, int n_in,
                              void* d_out, int out_size)
{
    const float* x      = (const float*)d_in[0];
    const float* w_qkv  = (const float*)d_in[1];
    const float* b_qkv  = (const float*)d_in[2];
    const float* w_proj = (const float*)d_in[3];
    const float* b_proj = (const float*)d_in[4];
    float* out = (float*)d_out;

    // 1) QKV GEMM + scatter into [b,h,t,d] Q/K/V
    dim3 g1(3 * CEMB / GBN, MROWS / GBM);   // 24 x 64
    gemm_f32x2<0><<<g1, 256>>>(x, w_qkv, b_qkv, nullptr, 3 * CEMB, CEMB);

    // 2) block-sparse flash attention
    cudaFuncSetAttribute(attn_kernel,
                         cudaFuncAttributeMaxDynamicSharedMemorySize, ATTN_SMEM);
    attn_kernel<<<dim3(TSEQ / BQ, BATCH * NH), 512, ATTN_SMEM>>>();

    // 3) output projection
    dim3 g3(CEMB / GBN, MROWS / GBM);       // 8 x 64
    gemm_f32x2<1><<<g3, 256>>>(nullptr, w_proj, b_proj, out, CEMB, CEMB);
}

// round 3
// speedup vs baseline: 1.7069x; 1.7069x over previous
#include <cuda_runtime.h>
#include <cuda_bf16.h>
#include <cstdint>
#include <math.h>

#define BATCH 2
#define TSEQ  4096
#define NH    16
#define HD    64
#define CEMB  1024
#define MROWS (BATCH*TSEQ)          // 8192
#define SCALE 0.125f                // 1/sqrt(64)

// ---------------- scratch (device globals: no runtime allocation) ------------
__device__ float g_Q[(size_t)BATCH*NH*TSEQ*HD];
__device__ float g_K[(size_t)BATCH*NH*TSEQ*HD];
__device__ float g_V[(size_t)BATCH*NH*TSEQ*HD];
__device__ float g_Y[(size_t)BATCH*TSEQ*CEMB];

// bf16 hi/lo split operands for tensor-core GEMMs
__device__ __nv_bfloat16 g_xh[(size_t)MROWS*CEMB];
__device__ __nv_bfloat16 g_xl[(size_t)MROWS*CEMB];
__device__ __nv_bfloat16 g_yh[(size_t)MROWS*CEMB];
__device__ __nv_bfloat16 g_yl[(size_t)MROWS*CEMB];
// weights stored TRANSPOSED: [N, K] K-major
__device__ __nv_bfloat16 g_wqh[(size_t)3*CEMB*CEMB];
__device__ __nv_bfloat16 g_wql[(size_t)3*CEMB*CEMB];
__device__ __nv_bfloat16 g_wph[(size_t)CEMB*CEMB];
__device__ __nv_bfloat16 g_wpl[(size_t)CEMB*CEMB];

// ---------------- PTX helpers (sm_80-era only: safe for plain sm_103) --------
__device__ __forceinline__ uint32_t smem_u32(const void* p) {
    uint32_t a;
    asm("{ .reg .u64 t; cvta.to.shared.u64 t, %1; cvt.u32.u64 %0, t; }"
        : "=r"(a) : "l"(p));
    return a;
}
__device__ __forceinline__ void cpasync16(uint32_t saddr, const void* g) {
    asm volatile("cp.async.cg.shared.global [%0], [%1], 16;"
                 :: "r"(saddr), "l"(g) : "memory");
}
#define CP_COMMIT() asm volatile("cp.async.commit_group;" ::: "memory")
#define CP_WAIT1()  asm volatile("cp.async.wait_group 1;" ::: "memory")

__device__ __forceinline__ void ldmx4(uint32_t* r, uint32_t addr) {
    asm volatile("ldmatrix.sync.aligned.m8n8.x4.shared.b16 {%0,%1,%2,%3}, [%4];"
        : "=r"(r[0]), "=r"(r[1]), "=r"(r[2]), "=r"(r[3]) : "r"(addr));
}
__device__ __forceinline__ void ldmx2(uint32_t* r, uint32_t addr) {
    asm volatile("ldmatrix.sync.aligned.m8n8.x2.shared.b16 {%0,%1}, [%2];"
        : "=r"(r[0]), "=r"(r[1]) : "r"(addr));
}
__device__ __forceinline__ void mma16816(float* d, const uint32_t* a,
                                         const uint32_t* b) {
    asm volatile(
        "mma.sync.aligned.m16n8k16.row.col.f32.bf16.bf16.f32 "
        "{%0,%1,%2,%3}, {%4,%5,%6,%7}, {%8,%9}, {%0,%1,%2,%3};"
        : "+f"(d[0]), "+f"(d[1]), "+f"(d[2]), "+f"(d[3])
        : "r"(a[0]), "r"(a[1]), "r"(a[2]), "r"(a[3]), "r"(b[0]), "r"(b[1]));
}

// ---------------- hi/lo split conversion kernels ------------------------------
__device__ __forceinline__ void split1(float v, unsigned short& h, unsigned short& l) {
    __nv_bfloat16 hb = __float2bfloat16_rn(v);
    __nv_bfloat16 lb = __float2bfloat16_rn(v - __bfloat162float(hb));
    h = __bfloat16_as_ushort(hb);
    l = __bfloat16_as_ushort(lb);
}

template <int SRC>
__global__ void conv_split(const float* __restrict__ src, int n) {
    const float* s = (SRC == 1) ? (const float*)g_Y : src;
    __nv_bfloat16* hi = (SRC == 1) ? g_yh : g_xh;
    __nv_bfloat16* lo = (SRC == 1) ? g_yl : g_xl;
    int i = (blockIdx.x * 256 + threadIdx.x) * 4;
    if (i < n) {
        float4 v = *(const float4*)&s[i];
        ushort4 h, l;
        split1(v.x, h.x, l.x); split1(v.y, h.y, l.y);
        split1(v.z, h.z, l.z); split1(v.w, h.w, l.w);
        *(ushort4*)&hi[i] = h;
        *(ushort4*)&lo[i] = l;
    }
}

// transpose + split: w [K, N] row-major fp32 -> wT hi/lo [N, K] bf16
template <int W>
__global__ void conv_split_T(const float* __restrict__ w, int K, int N) {
    __shared__ float t[32][33];
    __nv_bfloat16* hiT = (W == 0) ? g_wqh : g_wph;
    __nv_bfloat16* loT = (W == 0) ? g_wql : g_wpl;
    int n0 = blockIdx.x * 32, k0 = blockIdx.y * 32;
    int tx = threadIdx.x & 31, ty = threadIdx.x >> 5;   // 32 x 8
    for (int r = ty; r < 32; r += 8)
        t[r][tx] = w[(size_t)(k0 + r) * N + n0 + tx];
    __syncthreads();
    for (int r = ty; r < 32; r += 8) {
        float v = t[tx][r];   // = w[k0+tx][n0+r]
        unsigned short h, l;
        split1(v, h, l);
        size_t o = (size_t)(n0 + r) * K + k0 + tx;
        hiT[o] = __ushort_as_bfloat16(h);
        loT[o] = __ushort_as_bfloat16(l);
    }
}

// ---------------- bf16x3 GEMM on mma.sync (HMMA) ------------------------------
// C[M=8192,N] = (Ah+Al)(Bh+Bl)^T + bias, dropping AlBl.
// CTA tile 128x128, BK=64, double-buffered cp.async, 8 warps in 2x4,
// warp tile 64x32 = 4x4 frags of m16n8k16, 3 mmas per frag per k16.
#define BK    64
#define KSTR  72                    // padded row: 72 bf16 = 144 B (ldmatrix conflict-free)
#define ROWB  (KSTR*2)
#define MATB  (128*ROWB)            // 18432 B
#define STAGEB (4*MATB)             // 73728 B
#define GSMEM (2*STAGEB)            // 147456 B

template <int MODE>
__global__ __launch_bounds__(256)
void gemm_mma(const float* __restrict__ bias, float* __restrict__ out)
{
    extern __shared__ __align__(16) char sm[];
    uint32_t smb = smem_u32(sm);

    const __nv_bfloat16* Ah = (MODE == 0) ? g_xh : g_yh;
    const __nv_bfloat16* Al = (MODE == 0) ? g_xl : g_yl;
    const __nv_bfloat16* Bh = (MODE == 0) ? g_wqh : g_wph;
    const __nv_bfloat16* Bl = (MODE == 0) ? g_wql : g_wpl;

    int tid = threadIdx.x;
    int wid = tid >> 5, lane = tid & 31;
    int wm = wid >> 2, wn = wid & 3;
    int mBase = blockIdx.y * 128, nBase = blockIdx.x * 128;

    float acc[4][4][4];
#pragma unroll
    for (int mi = 0; mi < 4; mi++)
#pragma unroll
        for (int ni = 0; ni < 4; ni++)
#pragma unroll
            for (int q = 0; q < 4; q++) acc[mi][ni][q] = 0.f;

    const __nv_bfloat16* mats[4] = { Ah, Al, Bh, Bl };

    // ---- stage loader: 4 matrices x 128 rows x 8 chunks(16B) ----
    auto load_stage = [&](int s, int kt) {
        int k0 = kt * BK;
#pragma unroll
        for (int m = 0; m < 4; m++) {
            const __nv_bfloat16* src = mats[m];
            int rbase = (m < 2) ? mBase : nBase;
            uint32_t sb = smb + s * STAGEB + m * MATB;
#pragma unroll
            for (int c = tid; c < 1024; c += 256) {
                int row = c >> 3, ch = c & 7;
                cpasync16(sb + row * ROWB + ch * 16,
                          src + (size_t)(rbase + row) * CEMB + k0 + ch * 8);
            }
        }
    };

    int g = lane >> 3, w = lane & 7;
    uint32_t a_row = (wm * 64 + ((g & 1) << 3) + w) * ROWB;
    uint32_t b_row = (wn * 32 + w) * ROWB;
    uint32_t ka_off = ((g >> 1) << 3) * 2;
    uint32_t kb_off = ((g & 1) << 3) * 2;

    load_stage(0, 0);
    CP_COMMIT();

    for (int kt = 0; kt < 16; kt++) {
        int s = kt & 1;
        if (kt + 1 < 16) load_stage((kt + 1) & 1, kt + 1);
        CP_COMMIT();
        CP_WAIT1();
        __syncthreads();

        uint32_t bAh = smb + s * STAGEB;
        uint32_t bAl = bAh + MATB;
        uint32_t bBh = bAl + MATB;
        uint32_t bBl = bBh + MATB;

#pragma unroll
        for (int ks = 0; ks < 4; ks++) {
            uint32_t ka = ks * 32 + ka_off;   // k0*2 bytes
            uint32_t kb = ks * 32 + kb_off;
            uint32_t ah[4][4], al[4][4], bh[4][2], bl[4][2];
#pragma unroll
            for (int mi = 0; mi < 4; mi++) {
                uint32_t ro = a_row + mi * 16 * ROWB;
                ldmx4(ah[mi], bAh + ro + ka);
                ldmx4(al[mi], bAl + ro + ka);
            }
#pragma unroll
            for (int ni = 0; ni < 4; ni++) {
                uint32_t ro = b_row + ni * 8 * ROWB;
                ldmx2(bh[ni], bBh + ro + kb);
                ldmx2(bl[ni], bBl + ro + kb);
            }
#pragma unroll
            for (int mi = 0; mi < 4; mi++)
#pragma unroll
                for (int ni = 0; ni < 4; ni++) {
                    mma16816(acc[mi][ni], ah[mi], bh[ni]);
                    mma16816(acc[mi][ni], ah[mi], bl[ni]);
                    mma16816(acc[mi][ni], al[mi], bh[ni]);
                }
        }
        __syncthreads();
    }

    // ---- epilogue: bias add + store (MODE 0 scatters into Q/K/V) ----
    int r_in = lane >> 2, c_in = (lane & 3) * 2;
#pragma unroll
    for (int mi = 0; mi < 4; mi++) {
#pragma unroll
        for (int half = 0; half < 2; half++) {
            int m = mBase + wm * 64 + mi * 16 + r_in + half * 8;
#pragma unroll
            for (int ni = 0; ni < 4; ni++) {
                int n = nBase + wn * 32 + ni * 8 + c_in;
                float v0 = acc[mi][ni][half * 2 + 0] + bias[n];
                float v1 = acc[mi][ni][half * 2 + 1] + bias[n + 1];
                if (MODE == 0) {
                    int b = m >> 12, t = m & 4095;
                    int sect = n >> 10, cc = n & 1023;
                    int head = cc >> 6, d0 = cc & 63;
                    float* dst = (sect == 0) ? g_Q : (sect == 1) ? g_K : g_V;
                    *(float2*)&dst[(((size_t)b * NH + head) * TSEQ + t) * HD + d0] =
                        make_float2(v0, v1);
                } else {
                    *(float2*)&out[(size_t)m * CEMB + n] = make_float2(v0, v1);
                }
            }
        }
    }
}

// ---------------- block-sparse flash attention (fp32, unchanged) --------------
#define BQ    128
#define QSTR  68
#define KTSTR 132
#define VSTR  68
#define SSTR  132
#define ATTN_SMEM ((128*QSTR + 64*KTSTR + 128*VSTR + 128*SSTR + 3*128) * 4)

__global__ __launch_bounds__(512, 1)
void attn_kernel()
{
    extern __shared__ float smf[];
    float* Qs   = smf;
    float* Kt   = Qs + 128 * QSTR;
    float* Vs   = Kt + 64 * KTSTR;
    float* Ss   = Vs + 128 * VSTR;
    float* mrow = Ss + 128 * SSTR;
    float* lrow = mrow + 128;
    float* rsc  = lrow + 128;

    int tid = threadIdx.x;
    int qb = blockIdx.x;
    int bh = blockIdx.y;

    const float* Qg = g_Q + (size_t)bh * TSEQ * HD + (size_t)qb * BQ * HD;
    const float* Kg = g_K + (size_t)bh * TSEQ * HD;
    const float* Vg = g_V + (size_t)bh * TSEQ * HD;

#pragma unroll
    for (int e = tid; e < BQ * 16; e += 512) {
        int row = e >> 4, c4 = e & 15;
        *(float4*)&Qs[row * QSTR + c4 * 4] = *(const float4*)&Qg[row * HD + c4 * 4];
    }
    if (tid < 128) { mrow[tid] = -1e30f; lrow[tid] = 0.f; }

    float acc[4][4];
#pragma unroll
    for (int k = 0; k < 4; k++)
#pragma unroll
        for (int u = 0; u < 4; u++) acc[k][u] = 0.f;

    int rg = tid >> 4;
    int dq = tid & 15;

    __syncthreads();

    int kb_lo = (qb - 2 > 0) ? qb - 2 : 0;
    int ndense = (qb - kb_lo + 1) + ((kb_lo > 0) ? 1 : 0);
    for (int it = 0; it < ndense; it++) {
        int kb, jmax;
        if (it <= qb - kb_lo) { kb = kb_lo + it; jmax = 128; }
        else                  { kb = 0;          jmax = 16;  }

        for (int e = tid; e < jmax * 16; e += 512) {
            int row = e >> 4, c4 = e & 15;
            *(float4*)&Vs[row * VSTR + c4 * 4] =
                *(const float4*)&Vg[(size_t)(kb * BQ + row) * HD + c4 * 4];
        }
        for (int e = tid; e < jmax * 16; e += 512) {
            int row = e & (jmax - 1), c4 = e / jmax;
            float4 kvv = *(const float4*)&Kg[(size_t)(kb * BQ + row) * HD + c4 * 4];
            Kt[(c4 * 4 + 0) * KTSTR + row] = kvv.x;
            Kt[(c4 * 4 + 1) * KTSTR + row] = kvv.y;
            Kt[(c4 * 4 + 2) * KTSTR + row] = kvv.z;
            Kt[(c4 * 4 + 3) * KTSTR + row] = kvv.w;
        }
        __syncthreads();

        {
            int sy = tid >> 5, sx = tid & 31;
            int r0 = sy * 8, c0 = sx * 4;
            if (c0 < jmax) {
                float s[8][4];
#pragma unroll
                for (int ii = 0; ii < 8; ii++)
#pragma unroll
                    for (int jj = 0; jj < 4; jj++) s[ii][jj] = 0.f;
#pragma unroll 8
                for (int d = 0; d < HD; d++) {
                    float4 kv = *(const float4*)&Kt[d * KTSTR + c0];
#pragma unroll
                    for (int ii = 0; ii < 8; ii++) {
                        float qv = Qs[(r0 + ii) * QSTR + d];
                        s[ii][0] += qv * kv.x;
                        s[ii][1] += qv * kv.y;
                        s[ii][2] += qv * kv.z;
                        s[ii][3] += qv * kv.w;
                    }
                }
                int ib = qb * BQ;
#pragma unroll
                for (int ii = 0; ii < 8; ii++) {
                    int i = ib + r0 + ii;
                    float ov[4];
#pragma unroll
                    for (int jj = 0; jj < 4; jj++) {
                        int j = kb * BQ + c0 + jj;
                        int diff = i - j;
                        bool ok = (diff >= 0) &&
                                  ((diff < 256) || ((diff & 127) == 0) || (j < 16));
                        ov[jj] = ok ? s[ii][jj] * SCALE : -1e30f;
                    }
                    *(float4*)&Ss[(r0 + ii) * SSTR + c0] =
                        make_float4(ov[0], ov[1], ov[2], ov[3]);
                }
            }
        }
        __syncthreads();

        {
            int r = tid >> 2, part = tid & 3;
            int jbeg = part * 32;
            int jend = (jbeg + 32 < jmax) ? jbeg + 32 : jmax;
            float mx = -1e30f;
            for (int j = jbeg; j < jend; j++) mx = fmaxf(mx, Ss[r * SSTR + j]);
            mx = fmaxf(mx, __shfl_xor_sync(0xffffffffu, mx, 1));
            mx = fmaxf(mx, __shfl_xor_sync(0xffffffffu, mx, 2));
            float mold = mrow[r];
            float mnew = fmaxf(mold, mx);
            float cs = __expf(mold - mnew);
            float sum = 0.f;
            for (int j = jbeg; j < jend; j++) {
                float p = __expf(Ss[r * SSTR + j] - mnew);
                Ss[r * SSTR + j] = p;
                sum += p;
            }
            sum += __shfl_xor_sync(0xffffffffu, sum, 1);
            sum += __shfl_xor_sync(0xffffffffu, sum, 2);
            if (part == 0) {
                mrow[r] = mnew;
                lrow[r] = lrow[r] * cs + sum;
                rsc[r] = cs;
            }
        }
        __syncthreads();

        {
#pragma unroll
            for (int k = 0; k < 4; k++) {
                float cs = rsc[rg * 4 + k];
                acc[k][0] *= cs; acc[k][1] *= cs; acc[k][2] *= cs; acc[k][3] *= cs;
            }
            for (int j = 0; j < jmax; j += 4) {
                float pv[4][4];
#pragma unroll
                for (int k = 0; k < 4; k++)
                    *(float4*)&pv[k][0] = *(const float4*)&Ss[(rg * 4 + k) * SSTR + j];
#pragma unroll
                for (int u = 0; u < 4; u++) {
                    float4 v = *(const float4*)&Vs[(j + u) * VSTR + dq * 4];
#pragma unroll
                    for (int k = 0; k < 4; k++) {
                        float p = pv[k][u];
                        acc[k][0] += p * v.x;
                        acc[k][1] += p * v.y;
                        acc[k][2] += p * v.z;
                        acc[k][3] += p * v.w;
                    }
                }
            }
        }
        __syncthreads();
    }

    int nkb = qb - 2;
    if (nkb > 0) {
        int r = tid >> 2, part = tid & 3;
        for (int kb = 0; kb < nkb; kb++) {
            if (kb == 0 && r < 16) {
                if (part == 0) Ss[r * SSTR + kb] = -1e30f;
            } else {
                int j = kb * BQ + r;
                const float* kp = &Kg[(size_t)j * HD + part * 16];
                const float* qp = &Qs[r * QSTR + part * 16];
                float ps = 0.f;
#pragma unroll
                for (int u = 0; u < 4; u++) {
                    float4 a = *(const float4*)&kp[u * 4];
                    float4 b = *(const float4*)&qp[u * 4];
                    ps += a.x * b.x + a.y * b.y + a.z * b.z + a.w * b.w;
                }
                ps += __shfl_xor_sync(0xffffffffu, ps, 1);
                ps += __shfl_xor_sync(0xffffffffu, ps, 2);
                if (part == 0) Ss[r * SSTR + kb] = ps * SCALE;
            }
        }
        __syncthreads();

        if (tid < 128) {
            int rr = tid;
            float mold = mrow[rr];
            float mx = mold;
            for (int kb = 0; kb < nkb; kb++) mx = fmaxf(mx, Ss[rr * SSTR + kb]);
            float cs = __expf(mold - mx);
            float sum = 0.f;
            for (int kb = 0; kb < nkb; kb++) {
                float p = __expf(Ss[rr * SSTR + kb] - mx);
                Ss[rr * SSTR + kb] = p;
                sum += p;
            }
            mrow[rr] = mx;
            lrow[rr] = lrow[rr] * cs + sum;
            rsc[rr] = cs;
        }
        __syncthreads();

#pragma unroll
        for (int k = 0; k < 4; k++) {
            float cs = rsc[rg * 4 + k];
            acc[k][0] *= cs; acc[k][1] *= cs; acc[k][2] *= cs; acc[k][3] *= cs;
        }
        for (int kb = 0; kb < nkb; kb++) {
#pragma unroll
            for (int k = 0; k < 4; k++) {
                int rr = rg * 4 + k;
                float p = Ss[rr * SSTR + kb];
                float4 v = *(const float4*)&Vg[(size_t)(kb * BQ + rr) * HD + dq * 4];
                acc[k][0] += p * v.x;
                acc[k][1] += p * v.y;
                acc[k][2] += p * v.z;
                acc[k][3] += p * v.w;
            }
        }
    }

    int b = bh >> 4, h = bh & 15;
#pragma unroll
    for (int k = 0; k < 4; k++) {
        int rr = rg * 4 + k;
        float inv = 1.f / lrow[rr];
        int i = qb * BQ + rr;
        float4 o = make_float4(acc[k][0] * inv, acc[k][1] * inv,
                               acc[k][2] * inv, acc[k][3] * inv);
        *(float4*)&g_Y[((size_t)b * TSEQ + i) * CEMB + h * HD + dq * 4] = o;
    }
}

// ---------------- launch -----------------------------------------------------
extern "C" void kernel_launch(void* const* d_in, const int* in_sizes, int n_in,
                              void* d_out, int out_size)
{
    const float* x      = (const float*)d_in[0];
    const float* w_qkv  = (const float*)d_in[1];
    const float* b_qkv  = (const float*)d_in[2];
    const float* w_proj = (const float*)d_in[3];
    const float* b_proj = (const float*)d_in[4];
    float* out = (float*)d_out;

    cudaFuncSetAttribute(gemm_mma<0>,
                         cudaFuncAttributeMaxDynamicSharedMemorySize, GSMEM);
    cudaFuncSetAttribute(gemm_mma<1>,
                         cudaFuncAttributeMaxDynamicSharedMemorySize, GSMEM);
    cudaFuncSetAttribute(attn_kernel,
                         cudaFuncAttributeMaxDynamicSharedMemorySize, ATTN_SMEM);

    // 0) hi/lo splits of inputs and (transposed) weights
    int n_x = MROWS * CEMB;
    conv_split<0><<<n_x / 4 / 256, 256>>>(x, n_x);
    conv_split_T<0><<<dim3(3 * CEMB / 32, CEMB / 32), 256>>>(w_qkv, CEMB, 3 * CEMB);
    conv_split_T<1><<<dim3(CEMB / 32, CEMB / 32), 256>>>(w_proj, CEMB, CEMB);

    // 1) QKV GEMM (HMMA bf16x3) -> g_Q/g_K/g_V
    gemm_mma<0><<<dim3(3 * CEMB / 128, MROWS / 128), 256, GSMEM>>>(b_qkv, nullptr);

    // 2) block-sparse flash attention -> g_Y
    attn_kernel<<<dim3(TSEQ / BQ, BATCH * NH), 512, ATTN_SMEM>>>();

    // 3) split Y, output projection (HMMA bf16x3) -> out
    conv_split<1><<<n_x / 4 / 256, 256>>>(nullptr, n_x);
    gemm_mma<1><<<dim3(CEMB / 128, MROWS / 128), 256, GSMEM>>>(b_proj, out);
}

// round 4
// speedup vs baseline: 2.1098x; 1.2361x over previous
#include <cuda_runtime.h>
#include <cuda_bf16.h>
#include <cstdint>
#include <math.h>

#define BATCH 2
#define TSEQ  4096
#define NH    16
#define HD    64
#define CEMB  1024
#define MROWS (BATCH*TSEQ)          // 8192
#define SCALE 0.125f                // 1/sqrt(64)

// ---------------- scratch (device globals: no runtime allocation) ------------
// bf16 hi/lo split operands everywhere
__device__ __nv_bfloat16 g_xh[(size_t)MROWS*CEMB];
__device__ __nv_bfloat16 g_xl[(size_t)MROWS*CEMB];
__device__ __nv_bfloat16 g_yh[(size_t)MROWS*CEMB];
__device__ __nv_bfloat16 g_yl[(size_t)MROWS*CEMB];
__device__ __nv_bfloat16 g_wqh[(size_t)3*CEMB*CEMB];   // [N,K] K-major
__device__ __nv_bfloat16 g_wql[(size_t)3*CEMB*CEMB];
__device__ __nv_bfloat16 g_wph[(size_t)CEMB*CEMB];
__device__ __nv_bfloat16 g_wpl[(size_t)CEMB*CEMB];
// Q/K/V in [bh][t][d] layout, bf16 hi/lo
__device__ __nv_bfloat16 g_qh[(size_t)BATCH*NH*TSEQ*HD];
__device__ __nv_bfloat16 g_ql[(size_t)BATCH*NH*TSEQ*HD];
__device__ __nv_bfloat16 g_kh[(size_t)BATCH*NH*TSEQ*HD];
__device__ __nv_bfloat16 g_kl[(size_t)BATCH*NH*TSEQ*HD];
__device__ __nv_bfloat16 g_vh[(size_t)BATCH*NH*TSEQ*HD];
__device__ __nv_bfloat16 g_vl[(size_t)BATCH*NH*TSEQ*HD];

// ---------------- PTX helpers (sm_80-era only) --------------------------------
__device__ __forceinline__ uint32_t smem_u32(const void* p) {
    uint32_t a;
    asm("{ .reg .u64 t; cvta.to.shared.u64 t, %1; cvt.u32.u64 %0, t; }"
        : "=r"(a) : "l"(p));
    return a;
}
__device__ __forceinline__ void cpasync16(uint32_t saddr, const void* g) {
    asm volatile("cp.async.cg.shared.global [%0], [%1], 16;"
                 :: "r"(saddr), "l"(g) : "memory");
}
#define CP_COMMIT() asm volatile("cp.async.commit_group;" ::: "memory")
#define CP_WAIT1()  asm volatile("cp.async.wait_group 1;" ::: "memory")
#define CP_WAIT0()  asm volatile("cp.async.wait_group 0;" ::: "memory")

__device__ __forceinline__ void ldmx4(uint32_t* r, uint32_t addr) {
    asm volatile("ldmatrix.sync.aligned.m8n8.x4.shared.b16 {%0,%1,%2,%3}, [%4];"
        : "=r"(r[0]), "=r"(r[1]), "=r"(r[2]), "=r"(r[3]) : "r"(addr));
}
__device__ __forceinline__ void ldmx2(uint32_t* r, uint32_t addr) {
    asm volatile("ldmatrix.sync.aligned.m8n8.x2.shared.b16 {%0,%1}, [%2];"
        : "=r"(r[0]), "=r"(r[1]) : "r"(addr));
}
__device__ __forceinline__ void ldmx4t(uint32_t* r, uint32_t addr) {
    asm volatile("ldmatrix.sync.aligned.m8n8.x4.trans.shared.b16 {%0,%1,%2,%3}, [%4];"
        : "=r"(r[0]), "=r"(r[1]), "=r"(r[2]), "=r"(r[3]) : "r"(addr));
}
__device__ __forceinline__ void mma16816(float* d, const uint32_t* a,
                                         const uint32_t* b) {
    asm volatile(
        "mma.sync.aligned.m16n8k16.row.col.f32.bf16.bf16.f32 "
        "{%0,%1,%2,%3}, {%4,%5,%6,%7}, {%8,%9}, {%0,%1,%2,%3};"
        : "+f"(d[0]), "+f"(d[1]), "+f"(d[2]), "+f"(d[3])
        : "r"(a[0]), "r"(a[1]), "r"(a[2]), "r"(a[3]), "r"(b[0]), "r"(b[1]));
}

__device__ __forceinline__ float2 bf2f(uint32_t u) {
    __nv_bfloat162 b = *(__nv_bfloat162*)&u;
    return __bfloat1622float2(b);
}
__device__ __forceinline__ uint32_t packbf(float x, float y) {
    __nv_bfloat162 t = __floats2bfloat162_rn(x, y);
    return *(uint32_t*)&t;
}
__device__ __forceinline__ void split1(float v, unsigned short& h, unsigned short& l) {
    __nv_bfloat16 hb = __float2bfloat16_rn(v);
    __nv_bfloat16 lb = __float2bfloat16_rn(v - __bfloat162float(hb));
    h = __bfloat16_as_ushort(hb);
    l = __bfloat16_as_ushort(lb);
}

// ---------------- conversion kernels ------------------------------------------
__global__ void conv_split_x(const float* __restrict__ src, int n) {
    int i = (blockIdx.x * 256 + threadIdx.x) * 4;
    if (i < n) {
        float4 v = *(const float4*)&src[i];
        ushort4 h, l;
        split1(v.x, h.x, l.x); split1(v.y, h.y, l.y);
        split1(v.z, h.z, l.z); split1(v.w, h.w, l.w);
        *(ushort4*)&g_xh[i] = h;
        *(ushort4*)&g_xl[i] = l;
    }
}
template <int W>
__global__ void conv_split_T(const float* __restrict__ w, int K, int N) {
    __shared__ float t[32][33];
    __nv_bfloat16* hiT = (W == 0) ? g_wqh : g_wph;
    __nv_bfloat16* loT = (W == 0) ? g_wql : g_wpl;
    int n0 = blockIdx.x * 32, k0 = blockIdx.y * 32;
    int tx = threadIdx.x & 31, ty = threadIdx.x >> 5;
    for (int r = ty; r < 32; r += 8)
        t[r][tx] = w[(size_t)(k0 + r) * N + n0 + tx];
    __syncthreads();
    for (int r = ty; r < 32; r += 8) {
        float v = t[tx][r];
        unsigned short h, l;
        split1(v, h, l);
        size_t o = (size_t)(n0 + r) * K + k0 + tx;
        hiT[o] = __ushort_as_bfloat16(h);
        loT[o] = __ushort_as_bfloat16(l);
    }
}

// ---------------- bf16x3 GEMM on mma.sync, 3-stage cp.async -------------------
#define BK    64
#define KSTR  72
#define ROWB  (KSTR*2)              // 144 B rows
#define MATB  (128*ROWB)            // 18432 B
#define STAGEB (4*MATB)             // 73728 B
#define GSMEM (3*STAGEB)            // 221184 B

template <int MODE>
__global__ __launch_bounds__(256)
void gemm_mma(const float* __restrict__ bias, float* __restrict__ out)
{
    extern __shared__ __align__(16) char sm[];
    uint32_t smb = smem_u32(sm);

    const __nv_bfloat16* Ah = (MODE == 0) ? g_xh : g_yh;
    const __nv_bfloat16* Al = (MODE == 0) ? g_xl : g_yl;
    const __nv_bfloat16* Bh = (MODE == 0) ? g_wqh : g_wph;
    const __nv_bfloat16* Bl = (MODE == 0) ? g_wql : g_wpl;

    int tid = threadIdx.x;
    int wid = tid >> 5, lane = tid & 31;
    int wm = wid >> 2, wn = wid & 3;
    int mBase = blockIdx.y * 128, nBase = blockIdx.x * 128;

    float acc[4][4][4];
#pragma unroll
    for (int mi = 0; mi < 4; mi++)
#pragma unroll
        for (int ni = 0; ni < 4; ni++)
#pragma unroll
            for (int q = 0; q < 4; q++) acc[mi][ni][q] = 0.f;

    const __nv_bfloat16* mats[4] = { Ah, Al, Bh, Bl };

    auto load_stage = [&](int st, int kt) {
        int k0 = kt * BK;
#pragma unroll
        for (int m = 0; m < 4; m++) {
            const __nv_bfloat16* src = mats[m];
            int rbase = (m < 2) ? mBase : nBase;
            uint32_t sb = smb + st * STAGEB + m * MATB;
#pragma unroll
            for (int c = tid; c < 1024; c += 256) {
                int row = c >> 3, ch = c & 7;
                cpasync16(sb + row * ROWB + ch * 16,
                          src + (size_t)(rbase + row) * CEMB + k0 + ch * 8);
            }
        }
    };

    int g = lane >> 3, w = lane & 7;
    uint32_t a_row = (wm * 64 + ((g & 1) << 3) + w) * ROWB;
    uint32_t b_row = (wn * 32 + w) * ROWB;
    uint32_t ka_off = ((g >> 1) << 3) * 2;
    uint32_t kb_off = ((g & 1) << 3) * 2;

    load_stage(0, 0); CP_COMMIT();
    load_stage(1, 1); CP_COMMIT();

    for (int kt = 0; kt < 16; kt++) {
        if (kt < 15) CP_WAIT1(); else CP_WAIT0();
        __syncthreads();
        if (kt + 2 < 16) { load_stage((kt + 2) % 3, kt + 2); CP_COMMIT(); }

        int s = kt % 3;
        uint32_t bAh = smb + s * STAGEB;
        uint32_t bAl = bAh + MATB;
        uint32_t bBh = bAl + MATB;
        uint32_t bBl = bBh + MATB;

#pragma unroll
        for (int ks = 0; ks < 4; ks++) {
            uint32_t ka = ks * 32 + ka_off;
            uint32_t kb = ks * 32 + kb_off;
            uint32_t ah[4][4], al[4][4], bh[4][2], bl[4][2];
#pragma unroll
            for (int mi = 0; mi < 4; mi++) {
                uint32_t ro = a_row + mi * 16 * ROWB;
                ldmx4(ah[mi], bAh + ro + ka);
                ldmx4(al[mi], bAl + ro + ka);
            }
#pragma unroll
            for (int ni = 0; ni < 4; ni++) {
                uint32_t ro = b_row + ni * 8 * ROWB;
                ldmx2(bh[ni], bBh + ro + kb);
                ldmx2(bl[ni], bBl + ro + kb);
            }
#pragma unroll
            for (int mi = 0; mi < 4; mi++)
#pragma unroll
                for (int ni = 0; ni < 4; ni++) {
                    mma16816(acc[mi][ni], ah[mi], bh[ni]);
                    mma16816(acc[mi][ni], ah[mi], bl[ni]);
                    mma16816(acc[mi][ni], al[mi], bh[ni]);
                }
        }
    }

    // epilogue
    int r_in = lane >> 2, c_in = (lane & 3) * 2;
#pragma unroll
    for (int mi = 0; mi < 4; mi++) {
#pragma unroll
        for (int half = 0; half < 2; half++) {
            int m = mBase + wm * 64 + mi * 16 + r_in + half * 8;
#pragma unroll
            for (int ni = 0; ni < 4; ni++) {
                int n = nBase + wn * 32 + ni * 8 + c_in;
                float v0 = acc[mi][ni][half * 2 + 0] + bias[n];
                float v1 = acc[mi][ni][half * 2 + 1] + bias[n + 1];
                if (MODE == 0) {
                    // write bf16 hi/lo into Q/K/V [bh][t][d]
                    int b = m >> 12, t = m & 4095;
                    int sect = n >> 10, cc = n & 1023;
                    int head = cc >> 6, d0 = cc & 63;
                    unsigned short h0, l0, h1, l1;
                    split1(v0, h0, l0); split1(v1, h1, l1);
                    uint32_t hv = (uint32_t)h0 | ((uint32_t)h1 << 16);
                    uint32_t lv = (uint32_t)l0 | ((uint32_t)l1 << 16);
                    size_t off = (((size_t)(b * NH + head)) * TSEQ + t) * HD + d0;
                    __nv_bfloat16* dh = (sect == 0) ? g_qh : (sect == 1) ? g_kh : g_vh;
                    __nv_bfloat16* dl = (sect == 0) ? g_ql : (sect == 1) ? g_kl : g_vl;
                    *(uint32_t*)&dh[off] = hv;
                    *(uint32_t*)&dl[off] = lv;
                } else {
                    *(float2*)&out[(size_t)m * CEMB + n] = make_float2(v0, v1);
                }
            }
        }
    }
}

// ---------------- HMMA block-sparse flash attention ---------------------------
// grid (32 qb, 32 bh), 256 threads = 8 warps; warp owns rows [wid*16, +16).
#define SMQ_H  0
#define SMQ_L  18432
#define SMKV   36864
#define STAGEKV 73728
#define SST_OFF (SMKV + 2*STAGEKV)          // 184320
#define ATTN_SMEM2 (SST_OFF + 128*33*4)     // 201216

template <int NNI>
__device__ __forceinline__ void dense_block(
    uint32_t smb, uint32_t kst, int lane, int wid, int i0, int jb,
    float (&oacc)[8][4], float (&m)[2], float (&l)[2])
{
    const int NKK = NNI / 2;
    int g = lane >> 3, w = lane & 7;
    uint32_t arow = smb + SMQ_H + (wid * 16 + ((g & 1) << 3) + w) * 144;
    uint32_t ka = ((g >> 1) << 3) * 2;

    uint32_t qhf[4][4], qlf[4][4];
#pragma unroll
    for (int ks = 0; ks < 4; ks++) {
        ldmx4(qhf[ks], arow + ks * 32 + ka);
        ldmx4(qlf[ks], arow + 18432 + ks * 32 + ka);
    }

    float sacc[NNI][4];
#pragma unroll
    for (int ni = 0; ni < NNI; ni++)
#pragma unroll
        for (int q = 0; q < 4; q++) sacc[ni][q] = 0.f;

    uint32_t kboff = ((g & 1) << 3) * 2;
#pragma unroll
    for (int ni = 0; ni < NNI; ni++) {
        uint32_t brow = kst + (ni * 8 + w) * 144 + kboff;
#pragma unroll
        for (int ks = 0; ks < 4; ks++) {
            uint32_t bh2[2], bl2[2];
            ldmx2(bh2, brow + ks * 32);
            ldmx2(bl2, brow + 18432 + ks * 32);
            mma16816(sacc[ni], qhf[ks], bh2);
            mma16816(sacc[ni], qhf[ks], bl2);
            mma16816(sacc[ni], qlf[ks], bh2);
        }
    }

    // mask + scale, block max
    int c0 = (lane & 3) * 2;
    float mb0 = -1e30f, mb1 = -1e30f;
#pragma unroll
    for (int ni = 0; ni < NNI; ni++) {
        int jB = jb + ni * 8 + c0;
#pragma unroll
        for (int q = 0; q < 4; q++) {
            int jj = jB + (q & 1);
            int ii = (q < 2) ? i0 : i0 + 8;
            int diff = ii - jj;
            bool ok = diff >= 0 &&
                      (diff < 256 || (diff & 127) == 0 || jj < 16);
            sacc[ni][q] = ok ? sacc[ni][q] * SCALE : -1e30f;
        }
        mb0 = fmaxf(mb0, fmaxf(sacc[ni][0], sacc[ni][1]));
        mb1 = fmaxf(mb1, fmaxf(sacc[ni][2], sacc[ni][3]));
    }
    mb0 = fmaxf(mb0, __shfl_xor_sync(0xffffffffu, mb0, 1));
    mb0 = fmaxf(mb0, __shfl_xor_sync(0xffffffffu, mb0, 2));
    mb1 = fmaxf(mb1, __shfl_xor_sync(0xffffffffu, mb1, 1));
    mb1 = fmaxf(mb1, __shfl_xor_sync(0xffffffffu, mb1, 2));

    float mn0 = fmaxf(m[0], mb0), mn1 = fmaxf(m[1], mb1);
    float cs0 = __expf(m[0] - mn0), cs1 = __expf(m[1] - mn1);
    float ls0 = 0.f, ls1 = 0.f;
#pragma unroll
    for (int ni = 0; ni < NNI; ni++) {
        float p0 = __expf(sacc[ni][0] - mn0);
        float p1 = __expf(sacc[ni][1] - mn0);
        float p2 = __expf(sacc[ni][2] - mn1);
        float p3 = __expf(sacc[ni][3] - mn1);
        sacc[ni][0] = p0; sacc[ni][1] = p1; sacc[ni][2] = p2; sacc[ni][3] = p3;
        ls0 += p0 + p1; ls1 += p2 + p3;
    }
    ls0 += __shfl_xor_sync(0xffffffffu, ls0, 1);
    ls0 += __shfl_xor_sync(0xffffffffu, ls0, 2);
    ls1 += __shfl_xor_sync(0xffffffffu, ls1, 1);
    ls1 += __shfl_xor_sync(0xffffffffu, ls1, 2);
    l[0] = l[0] * cs0 + ls0; m[0] = mn0;
    l[1] = l[1] * cs1 + ls1; m[1] = mn1;
#pragma unroll
    for (int nd = 0; nd < 8; nd++) {
        oacc[nd][0] *= cs0; oacc[nd][1] *= cs0;
        oacc[nd][2] *= cs1; oacc[nd][3] *= cs1;
    }

    // PV: P (hi/lo from regs) x V (hi/lo via ldmatrix.trans)
    uint32_t vbase = kst + 2 * 18432;
    int jrow = ((g & 1) << 3) + w;
    int dcol = ((g >> 1) << 3) * 2;
#pragma unroll
    for (int kk = 0; kk < NKK; kk++) {
        float* s0 = sacc[2 * kk];
        float* s1 = sacc[2 * kk + 1];
        float h00 = __bfloat162float(__float2bfloat16_rn(s0[0]));
        float h01 = __bfloat162float(__float2bfloat16_rn(s0[1]));
        float h02 = __bfloat162float(__float2bfloat16_rn(s0[2]));
        float h03 = __bfloat162float(__float2bfloat16_rn(s0[3]));
        float h10 = __bfloat162float(__float2bfloat16_rn(s1[0]));
        float h11 = __bfloat162float(__float2bfloat16_rn(s1[1]));
        float h12 = __bfloat162float(__float2bfloat16_rn(s1[2]));
        float h13 = __bfloat162float(__float2bfloat16_rn(s1[3]));
        uint32_t pah[4], pal[4];
        pah[0] = packbf(h00, h01); pah[1] = packbf(h02, h03);
        pah[2] = packbf(h10, h11); pah[3] = packbf(h12, h13);
        pal[0] = packbf(s0[0] - h00, s0[1] - h01);
        pal[1] = packbf(s0[2] - h02, s0[3] - h03);
        pal[2] = packbf(s1[0] - h10, s1[1] - h11);
        pal[3] = packbf(s1[2] - h12, s1[3] - h13);
#pragma unroll
        for (int nd2 = 0; nd2 < 4; nd2++) {
            uint32_t addr = vbase + (kk * 16 + jrow) * 144 + nd2 * 32 + dcol;
            uint32_t vh4[4], vl4[4];
            ldmx4t(vh4, addr);
            ldmx4t(vl4, addr + 18432);
            mma16816(oacc[nd2 * 2], pah, vh4);
            mma16816(oacc[nd2 * 2], pah, vl4);
            mma16816(oacc[nd2 * 2], pal, vh4);
            mma16816(oacc[nd2 * 2 + 1], pah, vh4 + 2);
            mma16816(oacc[nd2 * 2 + 1], pah, vl4 + 2);
            mma16816(oacc[nd2 * 2 + 1], pal, vh4 + 2);
        }
    }
}

__global__ __launch_bounds__(256, 1)
void attn_mma()
{
    extern __shared__ __align__(16) char sm[];
    uint32_t smb = smem_u32(sm);
    int tid = threadIdx.x, lane = tid & 31, wid = tid >> 5;
    int qb = blockIdx.x, bh = blockIdx.y;

    size_t qoff = ((size_t)bh * TSEQ + (size_t)qb * 128) * HD;
    for (int c = tid; c < 1024; c += 256) {
        int row = c >> 3, ch = c & 7;
        *(uint4*)(sm + SMQ_H + row * 144 + ch * 16) =
            *(const uint4*)&g_qh[qoff + row * HD + ch * 8];
        *(uint4*)(sm + SMQ_L + row * 144 + ch * 16) =
            *(const uint4*)&g_ql[qoff + row * HD + ch * 8];
    }

    float oacc[8][4];
#pragma unroll
    for (int nd = 0; nd < 8; nd++)
#pragma unroll
        for (int q = 0; q < 4; q++) oacc[nd][q] = 0.f;
    float m[2] = { -1e30f, -1e30f }, l[2] = { 0.f, 0.f };

    int kb_lo = (qb - 2 > 0) ? qb - 2 : 0;
    int blocks[4], bcols[4], ndense = 0;
    for (int kb = kb_lo; kb <= qb; kb++) { blocks[ndense] = kb; bcols[ndense] = 128; ndense++; }
    if (kb_lo > 0) { blocks[ndense] = 0; bcols[ndense] = 16; ndense++; }

    auto stage_kv = [&](int st, int idx) {
        int kb = blocks[idx];
        int nr = (bcols[idx] == 128) ? 128 : 16;
        uint32_t base = smb + SMKV + st * STAGEKV;
        const __nv_bfloat16* srcs[4] = { g_kh, g_kl, g_vh, g_vl };
#pragma unroll
        for (int mm = 0; mm < 4; mm++) {
            const __nv_bfloat16* src =
                srcs[mm] + ((size_t)bh * TSEQ + (size_t)kb * 128) * HD;
            for (int c = tid; c < nr * 8; c += 256) {
                int row = c >> 3, ch = c & 7;
                cpasync16(base + mm * 18432 + row * 144 + ch * 16,
                          src + row * HD + ch * 8);
            }
        }
    };

    stage_kv(0, 0); CP_COMMIT();
    int i0 = qb * 128 + wid * 16 + (lane >> 2);

    for (int it = 0; it < ndense; it++) {
        __syncthreads();
        if (it + 1 < ndense) { stage_kv((it + 1) & 1, it + 1); CP_COMMIT(); CP_WAIT1(); }
        else CP_WAIT0();
        __syncthreads();
        uint32_t kst = smb + SMKV + (it & 1) * STAGEKV;
        if (bcols[it] == 128)
            dense_block<16>(smb, kst, lane, wid, i0, blocks[it] * 128, oacc, m, l);
        else
            dense_block<2>(smb, kst, lane, wid, i0, blocks[it] * 128, oacc, m, l);
    }

    // ---------------- strided diagonals (scalar, fp32 from hi+lo) ------------
    int nkb = qb - 2;
    float* Sst = (float*)(sm + SST_OFF);
    if (nkb > 0) {
        int part = lane & 3;
        // phase A: scores
        for (int pass = 0; pass < 2; pass++) {
            int rloc = wid * 16 + pass * 8 + (lane >> 2);
            for (int kb = 0; kb < nkb; kb++) {
                float sc;
                if (kb == 0 && rloc < 16) {
                    sc = -1e30f;
                } else {
                    int j = kb * 128 + rloc;
                    size_t kbase = ((size_t)bh * TSEQ + j) * HD + part * 16;
                    uint32_t qb0 = smb + SMQ_H + rloc * 144 + part * 32;
                    float sum = 0.f;
#pragma unroll
                    for (int seg = 0; seg < 2; seg++) {
                        uint32_t qh4[4], ql4[4];
                        asm volatile("ld.shared.v4.b32 {%0,%1,%2,%3}, [%4];"
                            : "=r"(qh4[0]), "=r"(qh4[1]), "=r"(qh4[2]), "=r"(qh4[3])
                            : "r"(qb0 + seg * 16));
                        asm volatile("ld.shared.v4.b32 {%0,%1,%2,%3}, [%4];"
                            : "=r"(ql4[0]), "=r"(ql4[1]), "=r"(ql4[2]), "=r"(ql4[3])
                            : "r"(qb0 + 18432 + seg * 16));
                        uint4 kh4 = *(const uint4*)&g_kh[kbase + seg * 8];
                        uint4 kl4 = *(const uint4*)&g_kl[kbase + seg * 8];
                        const uint32_t* khp = (const uint32_t*)&kh4;
                        const uint32_t* klp = (const uint32_t*)&kl4;
#pragma unroll
                        for (int u = 0; u < 4; u++) {
                            float2 qh2 = bf2f(qh4[u]), ql2 = bf2f(ql4[u]);
                            float2 kh2 = bf2f(khp[u]), kl2 = bf2f(klp[u]);
                            sum += (qh2.x + ql2.x) * (kh2.x + kl2.x);
                            sum += (qh2.y + ql2.y) * (kh2.y + kl2.y);
                        }
                    }
                    sum += __shfl_xor_sync(0xffffffffu, sum, 1);
                    sum += __shfl_xor_sync(0xffffffffu, sum, 2);
                    sc = sum * SCALE;
                }
                if (part == 0) Sst[rloc * 33 + kb] = sc;
            }
        }
        __syncwarp();

        // phase B: merge + gathered PV
#pragma unroll
        for (int h = 0; h < 2; h++) {
            int r = wid * 16 + (lane >> 2) + h * 8;
            float mo = m[h], mx = mo;
            for (int kb = 0; kb < nkb; kb++)
                mx = fmaxf(mx, Sst[r * 33 + kb]);
            float cs = __expf(mo - mx);
            float ls = 0.f;
#pragma unroll
            for (int nd = 0; nd < 8; nd++) {
                oacc[nd][h * 2 + 0] *= cs;
                oacc[nd][h * 2 + 1] *= cs;
            }
            for (int kb = 0; kb < nkb; kb++) {
                float p = __expf(Sst[r * 33 + kb] - mx);
                ls += p;
                if (p > 0.f) {
                    int j = kb * 128 + r;
                    size_t vb = ((size_t)bh * TSEQ + j) * HD;
#pragma unroll
                    for (int nd = 0; nd < 8; nd++) {
                        int d0 = nd * 8 + (lane & 3) * 2;
                        float2 vh = bf2f(*(const uint32_t*)&g_vh[vb + d0]);
                        float2 vl = bf2f(*(const uint32_t*)&g_vl[vb + d0]);
                        oacc[nd][h * 2 + 0] += p * (vh.x + vl.x);
                        oacc[nd][h * 2 + 1] += p * (vh.y + vl.y);
                    }
                }
            }
            m[h] = mx;
            l[h] = l[h] * cs + ls;
        }
    }

    // ---------------- epilogue: y -> hi/lo bf16 -------------------------------
    int b = bh >> 4, head = bh & 15;
#pragma unroll
    for (int h = 0; h < 2; h++) {
        float inv = 1.f / l[h];
        int i = qb * 128 + wid * 16 + (lane >> 2) + h * 8;
        size_t row_off = ((size_t)(b * TSEQ + i)) * CEMB + head * HD;
#pragma unroll
        for (int nd = 0; nd < 8; nd++) {
            int d0 = nd * 8 + (lane & 3) * 2;
            float y0 = oacc[nd][h * 2 + 0] * inv;
            float y1 = oacc[nd][h * 2 + 1] * inv;
            unsigned short h0, l0, h1, l1;
            split1(y0, h0, l0); split1(y1, h1, l1);
            *(uint32_t*)&g_yh[row_off + d0] = (uint32_t)h0 | ((uint32_t)h1 << 16);
            *(uint32_t*)&g_yl[row_off + d0] = (uint32_t)l0 | ((uint32_t)l1 << 16);
        }
    }
}

// ---------------- launch -----------------------------------------------------
extern "C" void kernel_launch(void* const* d_in, const int* in_sizes, int n_in,
                              void* d_out, int out_size)
{
    const float* x      = (const float*)d_in[0];
    const float* w_qkv  = (const float*)d_in[1];
    const float* b_qkv  = (const float*)d_in[2];
    const float* w_proj = (const float*)d_in[3];
    const float* b_proj = (const float*)d_in[4];
    float* out = (float*)d_out;

    cudaFuncSetAttribute(gemm_mma<0>,
                         cudaFuncAttributeMaxDynamicSharedMemorySize, GSMEM);
    cudaFuncSetAttribute(gemm_mma<1>,
                         cudaFuncAttributeMaxDynamicSharedMemorySize, GSMEM);
    cudaFuncSetAttribute(attn_mma,
                         cudaFuncAttributeMaxDynamicSharedMemorySize, ATTN_SMEM2);

    int n_x = MROWS * CEMB;
    conv_split_x<<<n_x / 4 / 256, 256>>>(x, n_x);
    conv_split_T<0><<<dim3(3 * CEMB / 32, CEMB / 32), 256>>>(w_qkv, CEMB, 3 * CEMB);
    conv_split_T<1><<<dim3(CEMB / 32, CEMB / 32), 256>>>(w_proj, CEMB, CEMB);

    // 1) QKV GEMM -> Q/K/V bf16 hi/lo
    gemm_mma<0><<<dim3(3 * CEMB / 128, MROWS / 128), 256, GSMEM>>>(b_qkv, nullptr);

    // 2) HMMA block-sparse flash attention -> yh/yl
    attn_mma<<<dim3(TSEQ / 128, BATCH * NH), 256, ATTN_SMEM2>>>();

    // 3) output projection -> out
    gemm_mma<1><<<dim3(CEMB / 128, MROWS / 128), 256, GSMEM>>>(b_proj, out);
}